// round 1
// baseline (speedup 1.0000x reference)
#include <cuda_runtime.h>
#include <cmath>

#define ZDIM 8192
#define QP   2016
#define KA0  4160
#define NOUT 448

// ---------------- device scratch (allocation-free: __device__ globals) ----------------
static __device__ float g_A0[(size_t)ZDIM * KA0];       // out0 features [z][4160]   (~136MB)
static __device__ float g_A2[(size_t)3 * ZDIM * QP];    // cross features [k][z][q]  (~198MB)
static __device__ float g_T [(size_t)ZDIM * 4096];      // T = s @ w3r   [z][m*64+w] (~134MB)
static __device__ float g_B0[KA0 * 64];                 // prescaled cat(w1,w2,w4,w5)
static __device__ float g_B6[QP * 64];                  // prescaled w6
static __device__ unsigned char g_iu[QP];
static __device__ unsigned char g_iv[QP];

// ---------------- tiny setup kernels ----------------
__global__ void init_tables_kernel() {
    int u = threadIdx.x;
    if (u < 63) {
        int idx = u * 63 - (u * (u - 1)) / 2;   // triu offset for row u
        for (int v = u + 1; v < 64; ++v) {
            g_iu[idx] = (unsigned char)u;
            g_iv[idx] = (unsigned char)v;
            ++idx;
        }
    }
}

__global__ void prep_weights_kernel(const float* __restrict__ w1, const float* __restrict__ w2,
                                    const float* __restrict__ w4, const float* __restrict__ w5,
                                    const float* __restrict__ w6,
                                    float c1, float c2, float c4s, float c5s, float c6s) {
    int i = blockIdx.x * blockDim.x + threadIdx.x;
    if (i < KA0 * 64) {
        int k = i >> 6;
        int w = i & 63;
        float val;
        if (k < QP)            val = c1  * w1[i];
        else if (k < QP + 64)  val = c2  * w2[((k - QP)   << 6) + w];
        else if (k < 4096)     val = c4s * w4[((k - 2080) << 6) + w];
        else                   val = c5s * w5[((k - 4096) << 6) + w];
        g_B0[i] = val;
    } else {
        int j = i - KA0 * 64;
        if (j < QP * 64) g_B6[j] = c6s * w6[j];
    }
}

// ---------------- feature generation: 8 z-rows per CTA, one z per warp ----------------
__global__ __launch_bounds__(256) void feature_kernel(const float* __restrict__ x) {
    __shared__ float xs[8][256];
    int tid = threadIdx.x;
    size_t zbase = (size_t)blockIdx.x * 8;
    const float4* xg = (const float4*)(x + zbase * 256);
    float4* xs4 = (float4*)xs;
    xs4[tid]       = xg[tid];
    xs4[tid + 256] = xg[tid + 256];
    __syncthreads();

    int wp   = tid >> 5;
    int lane = tid & 31;
    size_t z = zbase + wp;
    const float* s  = xs[wp];
    const float* vv = xs[wp] + 64;
    float* a0row  = g_A0 + z * KA0;
    float* a2row0 = g_A2 + z * QP;
    float* a2row1 = g_A2 + (size_t)ZDIM * QP + z * QP;
    float* a2row2 = g_A2 + (size_t)2 * ZDIM * QP + z * QP;

    for (int q = lane; q < QP; q += 32) {
        int u = g_iu[q];
        int t = g_iv[q];
        a0row[q] = s[u] * s[t];
        float ax = vv[u*3+0], ay = vv[u*3+1], az = vv[u*3+2];
        float bx = vv[t*3+0], by = vv[t*3+1], bz = vv[t*3+2];
        a0row[2080 + q] = ax*bx + ay*by + az*bz;
        a2row0[q] = ay*bz - az*by;
        a2row1[q] = az*bx - ax*bz;
        a2row2[q] = ax*by - ay*bx;
    }
    for (int u = lane; u < 64; u += 32) {
        float su = s[u];
        a0row[2016 + u] = su * su;
        float ax = vv[u*3+0], ay = vv[u*3+1], az = vv[u*3+2];
        a0row[4096 + u] = ax*ax + ay*ay + az*az;
    }
}

// ---------------- SGEMM: CTA tile 128x64, thread tile 8z x 4w, KC=16 ----------------
// EPI 0: T = s @ w3r            (A=x lda=256, B=w3 ldb=4096, C=g_T, K=64)
// EPI 1: out0 (+=)              (A=g_A0 lda=4160, B=g_B0, C=out cols 0..63, split-K 2x2080)
// EPI 2: out2 (+=)              (A=g_A2 as [24576][2016], B=g_B6, C=out cols 256.., split-K 2x1008)
template<int EPI>
__global__ __launch_bounds__(256) void gemm_kernel(const float* __restrict__ Aext,
                                                   const float* __restrict__ Bext,
                                                   float* __restrict__ Cext) {
    constexpr int LDA    = (EPI == 0) ? 256 : (EPI == 1 ? KA0 : QP);
    constexpr int LDB    = (EPI == 0) ? 4096 : 64;
    constexpr int KSPLIT = (EPI == 0) ? 64 : (EPI == 1 ? 2080 : 1008);
    constexpr int NCH    = KSPLIT / 16;

    __shared__ float As[16][132];
    __shared__ float Bs[16][64];

    const float* A = (EPI == 0) ? Aext : (EPI == 1 ? (const float*)g_A0 : (const float*)g_A2);
    const float* B = (EPI == 0) ? Bext : (EPI == 1 ? (const float*)g_B0 : (const float*)g_B6);

    int tid = threadIdx.x;
    int m0  = blockIdx.x * 128;
    int n0  = blockIdx.y * 64;
    int kstart = blockIdx.z * KSPLIT;

    int ar    = tid >> 1;          // A stage: z row 0..127
    int ahalf = (tid & 1) << 3;    // A stage: k sub-offset 0 or 8
    int kb    = tid >> 4;          // B stage: k row 0..15
    int wb    = (tid & 15) << 2;   // w group (stage + compute)
    int ty    = tid >> 4;          // compute: z group (8 rows)

    const float* Aptr = A + (size_t)(m0 + ar) * LDA + kstart + ahalf;
    const float* Bptr = B + (size_t)(kstart + kb) * LDB + n0 + wb;

    float4 ra0 = *(const float4*)(Aptr);
    float4 ra1 = *(const float4*)(Aptr + 4);
    float4 rb  = *(const float4*)(Bptr);

    float acc[8][4];
    #pragma unroll
    for (int i = 0; i < 8; ++i)
        #pragma unroll
        for (int j = 0; j < 4; ++j) acc[i][j] = 0.0f;

    for (int c = 0; c < NCH; ++c) {
        __syncthreads();
        As[ahalf+0][ar] = ra0.x; As[ahalf+1][ar] = ra0.y;
        As[ahalf+2][ar] = ra0.z; As[ahalf+3][ar] = ra0.w;
        As[ahalf+4][ar] = ra1.x; As[ahalf+5][ar] = ra1.y;
        As[ahalf+6][ar] = ra1.z; As[ahalf+7][ar] = ra1.w;
        *(float4*)&Bs[kb][wb] = rb;
        __syncthreads();
        if (c + 1 < NCH) {
            ra0 = *(const float4*)(Aptr + (c+1)*16);
            ra1 = *(const float4*)(Aptr + (c+1)*16 + 4);
            rb  = *(const float4*)(Bptr + (size_t)(c+1) * 16 * LDB);
        }
        #pragma unroll
        for (int kk = 0; kk < 16; ++kk) {
            float4 b  = *(const float4*)&Bs[kk][wb];
            float4 a0 = *(const float4*)&As[kk][ty * 8];
            float4 a1 = *(const float4*)&As[kk][ty * 8 + 4];
            acc[0][0] += a0.x*b.x; acc[0][1] += a0.x*b.y; acc[0][2] += a0.x*b.z; acc[0][3] += a0.x*b.w;
            acc[1][0] += a0.y*b.x; acc[1][1] += a0.y*b.y; acc[1][2] += a0.y*b.z; acc[1][3] += a0.y*b.w;
            acc[2][0] += a0.z*b.x; acc[2][1] += a0.z*b.y; acc[2][2] += a0.z*b.z; acc[2][3] += a0.z*b.w;
            acc[3][0] += a0.w*b.x; acc[3][1] += a0.w*b.y; acc[3][2] += a0.w*b.z; acc[3][3] += a0.w*b.w;
            acc[4][0] += a1.x*b.x; acc[4][1] += a1.x*b.y; acc[4][2] += a1.x*b.z; acc[4][3] += a1.x*b.w;
            acc[5][0] += a1.y*b.x; acc[5][1] += a1.y*b.y; acc[5][2] += a1.y*b.z; acc[5][3] += a1.y*b.w;
            acc[6][0] += a1.z*b.x; acc[6][1] += a1.z*b.y; acc[6][2] += a1.z*b.z; acc[6][3] += a1.z*b.w;
            acc[7][0] += a1.w*b.x; acc[7][1] += a1.w*b.y; acc[7][2] += a1.w*b.z; acc[7][3] += a1.w*b.w;
        }
    }

    if (EPI == 0) {
        #pragma unroll
        for (int i = 0; i < 8; ++i) {
            size_t row = (size_t)(m0 + ty * 8 + i);
            float4 v;
            v.x = acc[i][0]; v.y = acc[i][1]; v.z = acc[i][2]; v.w = acc[i][3];
            *(float4*)(g_T + row * 4096 + n0 + wb) = v;
        }
    } else if (EPI == 1) {
        #pragma unroll
        for (int i = 0; i < 8; ++i) {
            float* base = Cext + (size_t)(m0 + ty * 8 + i) * NOUT + wb;
            atomicAdd(base + 0, acc[i][0]);
            atomicAdd(base + 1, acc[i][1]);
            atomicAdd(base + 2, acc[i][2]);
            atomicAdd(base + 3, acc[i][3]);
        }
    } else {
        #pragma unroll
        for (int i = 0; i < 8; ++i) {
            int r  = m0 + ty * 8 + i;        // 0..24575
            int z  = r & (ZDIM - 1);
            int kp = r >> 13;                // cross component 0..2
            float* base = Cext + (size_t)z * NOUT + 256 + kp;
            atomicAdd(base + (wb + 0) * 3, acc[i][0]);
            atomicAdd(base + (wb + 1) * 3, acc[i][1]);
            atomicAdd(base + (wb + 2) * 3, acc[i][2]);
            atomicAdd(base + (wb + 3) * 3, acc[i][3]);
        }
    }
}

// ---------------- out1 contraction: out1[z,w,k] = (1/64) * sum_m T[z,m*64+w] * v[z,m,k] ----------------
__global__ __launch_bounds__(256) void out1_kernel(const float* __restrict__ x, float* __restrict__ out) {
    int tid  = threadIdx.x;
    int wp   = tid >> 5;
    int lane = tid & 31;
    size_t z = (size_t)blockIdx.x * 8 + wp;
    const float* Trow = g_T + z * 4096;
    const float* vp   = x + z * 256 + 64;
    float a00=0.f,a01=0.f,a02=0.f,a10=0.f,a11=0.f,a12=0.f;
    #pragma unroll 4
    for (int m = 0; m < 64; ++m) {
        float t0 = Trow[m * 64 + lane];
        float t1 = Trow[m * 64 + 32 + lane];
        float vx = vp[m*3+0], vy = vp[m*3+1], vz = vp[m*3+2];
        a00 += t0 * vx; a01 += t0 * vy; a02 += t0 * vz;
        a10 += t1 * vx; a11 += t1 * vy; a12 += t1 * vz;
    }
    float* base = out + z * NOUT + 64;
    const float sc = 0.015625f;   // 1/64 == C3/sqrt(3)
    base[lane*3+0]      = a00 * sc; base[lane*3+1]      = a01 * sc; base[lane*3+2]      = a02 * sc;
    base[(lane+32)*3+0] = a10 * sc; base[(lane+32)*3+1] = a11 * sc; base[(lane+32)*3+2] = a12 * sc;
}

// ---------------- launch ----------------
extern "C" void kernel_launch(void* const* d_in, const int* in_sizes, int n_in,
                              void* d_out, int out_size) {
    const float* x  = (const float*)d_in[0];
    const float* w1 = (const float*)d_in[1];
    const float* w2 = (const float*)d_in[2];
    const float* w3 = (const float*)d_in[3];
    const float* w4 = (const float*)d_in[4];
    const float* w5 = (const float*)d_in[5];
    const float* w6 = (const float*)d_in[6];
    float* out = (float*)d_out;

    const double X0 = 4160.0;
    float c1  = (float)sqrt(1.0 / X0);               // C1
    float c2  = (float)sqrt(1.0 / (3.0 * X0));       // C2
    float c4s = (float)sqrt(1.0 / (3.0 * X0));       // C4/sqrt(3)
    float c5s = (float)sqrt(1.0 / (15.0 * X0));      // C5/sqrt(3)
    float c6s = (float)sqrt(1.0 / 4032.0);           // C6/sqrt(6)

    cudaMemsetAsync(d_out, 0, (size_t)out_size * sizeof(float));
    init_tables_kernel<<<1, 64>>>();
    int total = KA0 * 64 + QP * 64;
    prep_weights_kernel<<<(total + 255) / 256, 256>>>(w1, w2, w4, w5, w6, c1, c2, c4s, c5s, c6s);
    feature_kernel<<<ZDIM / 8, 256>>>(x);

    gemm_kernel<0><<<dim3(64, 64, 1), 256>>>(x, w3, nullptr);        // T = s @ w3r
    gemm_kernel<1><<<dim3(64, 1, 2), 256>>>(nullptr, nullptr, out);  // out0, split-K=2
    gemm_kernel<2><<<dim3(192, 1, 2), 256>>>(nullptr, nullptr, out); // out2, split-K=2
    out1_kernel<<<ZDIM / 8, 256>>>(x, out);
}

// round 2
// speedup vs baseline: 1.0489x; 1.0489x over previous
#include <cuda_runtime.h>
#include <cmath>

#define ZDIM 8192
#define QP   2016
#define KA0  4160
#define NOUT 448

// ---------------- device scratch (allocation-free: __device__ globals) ----------------
static __device__ float g_A0[(size_t)ZDIM * KA0];       // out0 features [z][4160]   (~136MB)
static __device__ float g_A2[(size_t)3 * ZDIM * QP];    // cross features [k][z][q]  (~198MB)
static __device__ float g_T [(size_t)ZDIM * 4096];      // T = s @ w3r   [z][m*64+w] (~134MB)
static __device__ float g_B0[KA0 * 64];                 // prescaled cat(w1,w2,w4,w5)
static __device__ float g_B6[QP * 64];                  // prescaled w6
static __device__ unsigned char g_iu[QP];
static __device__ unsigned char g_iv[QP];

// ---------------- tiny setup kernels ----------------
__global__ void init_tables_kernel() {
    int u = threadIdx.x;
    if (u < 63) {
        int idx = u * 63 - (u * (u - 1)) / 2;   // triu offset for row u
        for (int v = u + 1; v < 64; ++v) {
            g_iu[idx] = (unsigned char)u;
            g_iv[idx] = (unsigned char)v;
            ++idx;
        }
    }
}

__global__ void prep_weights_kernel(const float* __restrict__ w1, const float* __restrict__ w2,
                                    const float* __restrict__ w4, const float* __restrict__ w5,
                                    const float* __restrict__ w6,
                                    float c1, float c2, float c4s, float c5s, float c6s) {
    int i = blockIdx.x * blockDim.x + threadIdx.x;
    if (i < KA0 * 64) {
        int k = i >> 6;
        int w = i & 63;
        float val;
        if (k < QP)            val = c1  * w1[i];
        else if (k < QP + 64)  val = c2  * w2[((k - QP)   << 6) + w];
        else if (k < 4096)     val = c4s * w4[((k - 2080) << 6) + w];
        else                   val = c5s * w5[((k - 4096) << 6) + w];
        g_B0[i] = val;
    } else {
        int j = i - KA0 * 64;
        if (j < QP * 64) g_B6[j] = c6s * w6[j];
    }
}

// ---------------- feature generation: 8 z-rows per CTA, one z per warp ----------------
__global__ __launch_bounds__(256) void feature_kernel(const float* __restrict__ x) {
    __shared__ float xs[8][256];
    int tid = threadIdx.x;
    size_t zbase = (size_t)blockIdx.x * 8;
    const float4* xg = (const float4*)(x + zbase * 256);
    float4* xs4 = (float4*)xs;
    xs4[tid]       = xg[tid];
    xs4[tid + 256] = xg[tid + 256];
    __syncthreads();

    int wp   = tid >> 5;
    int lane = tid & 31;
    size_t z = zbase + wp;
    const float* s  = xs[wp];
    const float* vv = xs[wp] + 64;
    float* a0row  = g_A0 + z * KA0;
    float* a2row0 = g_A2 + z * QP;
    float* a2row1 = g_A2 + (size_t)ZDIM * QP + z * QP;
    float* a2row2 = g_A2 + (size_t)2 * ZDIM * QP + z * QP;

    for (int q = lane; q < QP; q += 32) {
        int u = g_iu[q];
        int t = g_iv[q];
        a0row[q] = s[u] * s[t];
        float ax = vv[u*3+0], ay = vv[u*3+1], az = vv[u*3+2];
        float bx = vv[t*3+0], by = vv[t*3+1], bz = vv[t*3+2];
        a0row[2080 + q] = ax*bx + ay*by + az*bz;
        a2row0[q] = ay*bz - az*by;
        a2row1[q] = az*bx - ax*bz;
        a2row2[q] = ax*by - ay*bx;
    }
    for (int u = lane; u < 64; u += 32) {
        float su = s[u];
        a0row[2016 + u] = su * su;
        float ax = vv[u*3+0], ay = vv[u*3+1], az = vv[u*3+2];
        a0row[4096 + u] = ax*ax + ay*ay + az*az;
    }
}

// ---------------- SGEMM: CTA tile 128x64, thread tile 8z x 4w, KC=16 ----------------
// EPI 0: T = s @ w3r            (A=x lda=256, B=w3 ldb=4096, C=g_T, K=64)
// EPI 1: out0 (+=)              (A=g_A0 lda=4160, B=g_B0, C=out cols 0..63, split-K 2x2080)
// EPI 2: out2 (+=)              (A=g_A2 as [24576][2016], B=g_B6, C=out cols 256.., split-K 2x1008)
template<int EPI>
__global__ __launch_bounds__(256) void gemm_kernel(const float* __restrict__ Aext,
                                                   const float* __restrict__ Bext,
                                                   float* __restrict__ Cext) {
    constexpr int LDA    = (EPI == 0) ? 256 : (EPI == 1 ? KA0 : QP);
    constexpr int LDB    = (EPI == 0) ? 4096 : 64;
    constexpr int KSPLIT = (EPI == 0) ? 64 : (EPI == 1 ? 2080 : 1008);
    constexpr int NCH    = KSPLIT / 16;

    __shared__ float As[16][132];
    __shared__ float Bs[16][64];

    const float* A = (EPI == 0) ? Aext : (EPI == 1 ? (const float*)g_A0 : (const float*)g_A2);
    const float* B = (EPI == 0) ? Bext : (EPI == 1 ? (const float*)g_B0 : (const float*)g_B6);

    int tid = threadIdx.x;
    int m0  = blockIdx.x * 128;
    int n0  = blockIdx.y * 64;
    int kstart = blockIdx.z * KSPLIT;

    int ar    = tid >> 1;          // A stage: z row 0..127
    int ahalf = (tid & 1) << 3;    // A stage: k sub-offset 0 or 8
    int kb    = tid >> 4;          // B stage: k row 0..15
    int wb    = (tid & 15) << 2;   // w group (stage + compute)
    int ty    = tid >> 4;          // compute: z group (8 rows)

    const float* Aptr = A + (size_t)(m0 + ar) * LDA + kstart + ahalf;
    const float* Bptr = B + (size_t)(kstart + kb) * LDB + n0 + wb;

    float4 ra0 = *(const float4*)(Aptr);
    float4 ra1 = *(const float4*)(Aptr + 4);
    float4 rb  = *(const float4*)(Bptr);

    float acc[8][4];
    #pragma unroll
    for (int i = 0; i < 8; ++i)
        #pragma unroll
        for (int j = 0; j < 4; ++j) acc[i][j] = 0.0f;

    for (int c = 0; c < NCH; ++c) {
        __syncthreads();
        As[ahalf+0][ar] = ra0.x; As[ahalf+1][ar] = ra0.y;
        As[ahalf+2][ar] = ra0.z; As[ahalf+3][ar] = ra0.w;
        As[ahalf+4][ar] = ra1.x; As[ahalf+5][ar] = ra1.y;
        As[ahalf+6][ar] = ra1.z; As[ahalf+7][ar] = ra1.w;
        *(float4*)&Bs[kb][wb] = rb;
        __syncthreads();
        if (c + 1 < NCH) {
            ra0 = *(const float4*)(Aptr + (c+1)*16);
            ra1 = *(const float4*)(Aptr + (c+1)*16 + 4);
            rb  = *(const float4*)(Bptr + (size_t)(c+1) * 16 * LDB);
        }
        #pragma unroll
        for (int kk = 0; kk < 16; ++kk) {
            float4 b  = *(const float4*)&Bs[kk][wb];
            float4 a0 = *(const float4*)&As[kk][ty * 8];
            float4 a1 = *(const float4*)&As[kk][ty * 8 + 4];
            acc[0][0] += a0.x*b.x; acc[0][1] += a0.x*b.y; acc[0][2] += a0.x*b.z; acc[0][3] += a0.x*b.w;
            acc[1][0] += a0.y*b.x; acc[1][1] += a0.y*b.y; acc[1][2] += a0.y*b.z; acc[1][3] += a0.y*b.w;
            acc[2][0] += a0.z*b.x; acc[2][1] += a0.z*b.y; acc[2][2] += a0.z*b.z; acc[2][3] += a0.z*b.w;
            acc[3][0] += a0.w*b.x; acc[3][1] += a0.w*b.y; acc[3][2] += a0.w*b.z; acc[3][3] += a0.w*b.w;
            acc[4][0] += a1.x*b.x; acc[4][1] += a1.x*b.y; acc[4][2] += a1.x*b.z; acc[4][3] += a1.x*b.w;
            acc[5][0] += a1.y*b.x; acc[5][1] += a1.y*b.y; acc[5][2] += a1.y*b.z; acc[5][3] += a1.y*b.w;
            acc[6][0] += a1.z*b.x; acc[6][1] += a1.z*b.y; acc[6][2] += a1.z*b.z; acc[6][3] += a1.z*b.w;
            acc[7][0] += a1.w*b.x; acc[7][1] += a1.w*b.y; acc[7][2] += a1.w*b.z; acc[7][3] += a1.w*b.w;
        }
    }

    if (EPI == 0) {
        #pragma unroll
        for (int i = 0; i < 8; ++i) {
            size_t row = (size_t)(m0 + ty * 8 + i);
            float4 v;
            v.x = acc[i][0]; v.y = acc[i][1]; v.z = acc[i][2]; v.w = acc[i][3];
            *(float4*)(g_T + row * 4096 + n0 + wb) = v;
        }
    } else if (EPI == 1) {
        #pragma unroll
        for (int i = 0; i < 8; ++i) {
            float* base = Cext + (size_t)(m0 + ty * 8 + i) * NOUT + wb;
            atomicAdd(base + 0, acc[i][0]);
            atomicAdd(base + 1, acc[i][1]);
            atomicAdd(base + 2, acc[i][2]);
            atomicAdd(base + 3, acc[i][3]);
        }
    } else {
        #pragma unroll
        for (int i = 0; i < 8; ++i) {
            int r  = m0 + ty * 8 + i;        // 0..24575
            int z  = r & (ZDIM - 1);
            int kp = r >> 13;                // cross component 0..2
            float* base = Cext + (size_t)z * NOUT + 256 + kp;
            atomicAdd(base + (wb + 0) * 3, acc[i][0]);
            atomicAdd(base + (wb + 1) * 3, acc[i][1]);
            atomicAdd(base + (wb + 2) * 3, acc[i][2]);
            atomicAdd(base + (wb + 3) * 3, acc[i][3]);
        }
    }
}

// ---------------- out1 contraction: out1[z,w,k] = (1/64) * sum_m T[z,m*64+w] * v[z,m,k] ----------------
__global__ __launch_bounds__(256) void out1_kernel(const float* __restrict__ x, float* __restrict__ out) {
    int tid  = threadIdx.x;
    int wp   = tid >> 5;
    int lane = tid & 31;
    size_t z = (size_t)blockIdx.x * 8 + wp;
    const float* Trow = g_T + z * 4096;
    const float* vp   = x + z * 256 + 64;
    float a00=0.f,a01=0.f,a02=0.f,a10=0.f,a11=0.f,a12=0.f;
    #pragma unroll 4
    for (int m = 0; m < 64; ++m) {
        float t0 = Trow[m * 64 + lane];
        float t1 = Trow[m * 64 + 32 + lane];
        float vx = vp[m*3+0], vy = vp[m*3+1], vz = vp[m*3+2];
        a00 += t0 * vx; a01 += t0 * vy; a02 += t0 * vz;
        a10 += t1 * vx; a11 += t1 * vy; a12 += t1 * vz;
    }
    float* base = out + z * NOUT + 64;
    const float sc = 0.015625f;   // 1/64 == C3/sqrt(3)
    base[lane*3+0]      = a00 * sc; base[lane*3+1]      = a01 * sc; base[lane*3+2]      = a02 * sc;
    base[(lane+32)*3+0] = a10 * sc; base[(lane+32)*3+1] = a11 * sc; base[(lane+32)*3+2] = a12 * sc;
}

// ---------------- launch ----------------
extern "C" void kernel_launch(void* const* d_in, const int* in_sizes, int n_in,
                              void* d_out, int out_size) {
    const float* x  = (const float*)d_in[0];
    const float* w1 = (const float*)d_in[1];
    const float* w2 = (const float*)d_in[2];
    const float* w3 = (const float*)d_in[3];
    const float* w4 = (const float*)d_in[4];
    const float* w5 = (const float*)d_in[5];
    const float* w6 = (const float*)d_in[6];
    float* out = (float*)d_out;

    const double X0 = 4160.0;
    float c1  = (float)sqrt(1.0 / X0);               // C1
    float c2  = (float)sqrt(1.0 / (3.0 * X0));       // C2
    float c4s = (float)sqrt(1.0 / (3.0 * X0));       // C4/sqrt(3)
    float c5s = (float)sqrt(1.0 / (15.0 * X0));      // C5/sqrt(3)
    float c6s = (float)sqrt(1.0 / 4032.0);           // C6/sqrt(6)

    cudaMemsetAsync(d_out, 0, (size_t)out_size * sizeof(float));
    init_tables_kernel<<<1, 64>>>();
    int total = KA0 * 64 + QP * 64;
    prep_weights_kernel<<<(total + 255) / 256, 256>>>(w1, w2, w4, w5, w6, c1, c2, c4s, c5s, c6s);
    feature_kernel<<<ZDIM / 8, 256>>>(x);

    gemm_kernel<0><<<dim3(64, 64, 1), 256>>>(x, w3, nullptr);        // T = s @ w3r
    gemm_kernel<1><<<dim3(64, 1, 2), 256>>>(nullptr, nullptr, out);  // out0, split-K=2
    gemm_kernel<2><<<dim3(192, 1, 2), 256>>>(nullptr, nullptr, out); // out2, split-K=2
    out1_kernel<<<ZDIM / 8, 256>>>(x, out);
}